// round 8
// baseline (speedup 1.0000x reference)
#include <cuda_runtime.h>
#include <math.h>

#define NPTS 1024
#define TLEN 64
#define CDIM 256
#define NTILE 16                         // 1024 / 64
#define NBLK (NTILE * (NTILE + 1) / 2)   // 136 triangular tiles

typedef unsigned int uint32;

// Scratch (__device__ globals — no allocation allowed).
__device__ uint32 g_xtf[2][NPTS * CDIM]; // time-means pre-converted to tf32 bits
__device__ float  g_norm[2][NPTS];       // row squared norms (fp32 exact)
__device__ float  g_rs[2][NPTS];         // row sums of d (atomic-accumulated)
__device__ double g_acc[3];              // sum(dx*dy), sum(dx*dx), sum(dy*dy)
__device__ unsigned int g_ticket;        // last-block-done counter

__device__ __forceinline__ uint32 f2tf(float v) {
    uint32 r;
    asm("cvt.rna.tf32.f32 %0, %1;" : "=r"(r) : "f"(v));
    return r;
}
__device__ __forceinline__ void mma_tf32(float* c,
                                         uint32 a0, uint32 a1, uint32 a2, uint32 a3,
                                         uint32 b0, uint32 b1) {
    asm("mma.sync.aligned.m16n8k8.row.col.f32.tf32.tf32.f32 "
        "{%0,%1,%2,%3},{%4,%5,%6,%7},{%8,%9},{%0,%1,%2,%3};"
        : "+f"(c[0]), "+f"(c[1]), "+f"(c[2]), "+f"(c[3])
        : "r"(a0), "r"(a1), "r"(a2), "r"(a3), "r"(b0), "r"(b1));
}

// ---------------------------------------------------------------------------
// Kernel 1: time-mean over T + per-row squared norm + tf32 pre-conversion.
// grid (512, 2), block 256: 2 rows/block, 128 threads/row. HBM-ceiling bound.
// ---------------------------------------------------------------------------
__global__ void mean_norm_kernel(const float* __restrict__ a,
                                 const float* __restrict__ b) {
    const int w = blockIdx.y;
    const float* __restrict__ src = (w == 0) ? a : b;
    const int tid  = threadIdx.x;
    const int row  = tid >> 7;
    const int half = (tid >> 6) & 1;
    const int c4   = tid & 63;
    const int n    = blockIdx.x * 2 + row;

    if (blockIdx.x == 0) {   // fold init
#pragma unroll
        for (int r = 0; r < 4; ++r) g_rs[w][tid + 256 * r] = 0.f;
        if (w == 0 && tid == 0) {
            g_acc[0] = 0.0; g_acc[1] = 0.0; g_acc[2] = 0.0;
            g_ticket = 0u;
        }
    }

    const float4* __restrict__ p =
        (const float4*)(src + (size_t)n * (TLEN * CDIM)) + half * 32 * (CDIM / 4) + c4;
    float4 s0 = make_float4(0.f, 0.f, 0.f, 0.f);
    float4 s1 = make_float4(0.f, 0.f, 0.f, 0.f);
#pragma unroll
    for (int t = 0; t < 16; ++t) {
        float4 v0 = __ldcs(p + (size_t)(2 * t) * (CDIM / 4));
        float4 v1 = __ldcs(p + (size_t)(2 * t + 1) * (CDIM / 4));
        s0.x += v0.x; s0.y += v0.y; s0.z += v0.z; s0.w += v0.w;
        s1.x += v1.x; s1.y += v1.y; s1.z += v1.z; s1.w += v1.w;
    }
    float4 s;
    s.x = s0.x + s1.x; s.y = s0.y + s1.y; s.z = s0.z + s1.z; s.w = s0.w + s1.w;

    __shared__ float4 sh[2][2][64];
    __shared__ float part[2][2];
    sh[row][half][c4] = s;
    __syncthreads();

    if (half == 0) {
        const float4 o = sh[row][1][c4];
        const float inv = 1.0f / TLEN;
        float4 m;
        m.x = (s.x + o.x) * inv; m.y = (s.y + o.y) * inv;
        m.z = (s.z + o.z) * inv; m.w = (s.w + o.w) * inv;

        uint4 u;
        u.x = f2tf(m.x); u.y = f2tf(m.y); u.z = f2tf(m.z); u.w = f2tf(m.w);
        ((uint4*)(g_xtf[w] + (size_t)n * CDIM))[c4] = u;

        float sq = m.x * m.x + m.y * m.y + m.z * m.z + m.w * m.w;
#pragma unroll
        for (int off = 16; off > 0; off >>= 1)
            sq += __shfl_down_sync(0xffffffffu, sq, off);
        if ((c4 & 31) == 0) part[row][c4 >> 5] = sq;
    }
    __syncthreads();
    if ((tid & 127) == 0) g_norm[w][n] = part[row][0] + part[row][1];
}

// ---------------------------------------------------------------------------
// Kernel 2: triangular pairwise-distance GEMM on tensor cores (tf32 mma.sync)
// with MMA-PERMUTED shared layout: every fragment group is one LDS.128 at the
// lane's own address (conflict-free). 64x64 tile, 256 threads, 8 warps (4x2),
// fused statistics + ticket finalize. grid 136 = one wave.
//
// A layout: sA[kb][wr][lane=g*4+tig][q], q = 2*half + khalf holds element
//           (row 16*wr + 8*half + g, k = 8*kb + tig + 4*khalf)
// B layout: sB[kb][wc][tp][lane][q], q = 2*te + khalf holds element
//           (col 32*wc + 8*(2*tp+te) + g, k = 8*kb + tig + 4*khalf)
// ---------------------------------------------------------------------------
__global__ void __launch_bounds__(256) gemm_mma_kernel(float* __restrict__ out) {
    const int tb = blockIdx.x;
    int by = (int)((__fsqrt_rn(8.f * (float)tb + 1.f) - 1.f) * 0.5f);
    while ((by + 1) * (by + 2) / 2 <= tb) ++by;
    while (by * (by + 1) / 2 > tb) --by;
    const int bx = tb - by * (by + 1) / 2;
    const bool diag = (bx == by);
    const int I = bx * 64;   // rows
    const int J = by * 64;   // cols

    __shared__ uint32 sAx[4][4][32][4], sAy[4][4][32][4];       // 8KB each
    __shared__ uint32 sBx[4][2][2][32][4], sBy[4][2][2][32][4]; // 8KB each
    __shared__ float sh_rs[2][64], sh_cs[2][64];
    __shared__ float sh_p[3][8];
    __shared__ unsigned int s_last;

    const int tid  = threadIdx.x;
    const int warp = tid >> 5, lane = tid & 31;
    const int wr = warp >> 1, wc = warp & 1;   // 4x2 warp grid
    const int g = lane >> 2, tig = lane & 3;

    if (tid < 128) {
        const int w2 = tid >> 6;
        sh_rs[w2][tid & 63] = 0.f;
        sh_cs[w2][tid & 63] = 0.f;
    }

    float cx[4][4], cy[4][4];
#pragma unroll
    for (int t = 0; t < 4; ++t)
#pragma unroll
        for (int q = 0; q < 4; ++q) { cx[t][q] = 0.f; cy[t][q] = 0.f; }

    // fill mapping: m = tid>>2 (0..63) row, kb = tid&3 (8 consecutive k)
    const int m  = tid >> 2;
    const int kb = tid & 3;
    const int fg    = m & 7;            // lane row within 8
    const int fhalf = (m >> 3) & 1;     // A: which 8-row half of 16
    const int fwr   = m >> 4;           // A: warp-row block
    const int fwc   = m >> 5;           // B: warp-col block
    const int ft    = (m >> 3) & 3;     // B: 8-col group within 32
    const int ftp   = ft >> 1, fte = ft & 1;

    const uint32* __restrict__ XAx = g_xtf[0] + (size_t)(I + m) * CDIM + kb * 8;
    const uint32* __restrict__ XAy = g_xtf[1] + (size_t)(I + m) * CDIM + kb * 8;
    const uint32* __restrict__ XBx = g_xtf[0] + (size_t)(J + m) * CDIM + kb * 8;
    const uint32* __restrict__ XBy = g_xtf[1] + (size_t)(J + m) * CDIM + kb * 8;

    uint32 ax8[8], ay8[8], bx8[8], by8[8];
    *(uint4*)&ax8[0] = *(const uint4*)(XAx);     *(uint4*)&ax8[4] = *(const uint4*)(XAx + 4);
    *(uint4*)&ay8[0] = *(const uint4*)(XAy);     *(uint4*)&ay8[4] = *(const uint4*)(XAy + 4);
    *(uint4*)&bx8[0] = *(const uint4*)(XBx);     *(uint4*)&bx8[4] = *(const uint4*)(XBx + 4);
    *(uint4*)&by8[0] = *(const uint4*)(XBy);     *(uint4*)&by8[4] = *(const uint4*)(XBy + 4);

    for (int c = 0; c < 8; ++c) {
        __syncthreads();
#pragma unroll
        for (int q = 0; q < 4; ++q) {   // q == tig loop of the fill scatter
            uint2 va = make_uint2(ax8[q], ax8[q + 4]);
            *(uint2*)&sAx[kb][fwr][fg * 4 + q][2 * fhalf] = va;
            uint2 vay = make_uint2(ay8[q], ay8[q + 4]);
            *(uint2*)&sAy[kb][fwr][fg * 4 + q][2 * fhalf] = vay;
            uint2 vb = make_uint2(bx8[q], bx8[q + 4]);
            *(uint2*)&sBx[kb][fwc][ftp][fg * 4 + q][2 * fte] = vb;
            uint2 vby = make_uint2(by8[q], by8[q + 4]);
            *(uint2*)&sBy[kb][fwc][ftp][fg * 4 + q][2 * fte] = vby;
        }
        __syncthreads();
        if (c < 7) {
            const int k0 = (c + 1) * 32;
            *(uint4*)&ax8[0] = *(const uint4*)(XAx + k0);  *(uint4*)&ax8[4] = *(const uint4*)(XAx + k0 + 4);
            *(uint4*)&ay8[0] = *(const uint4*)(XAy + k0);  *(uint4*)&ay8[4] = *(const uint4*)(XAy + k0 + 4);
            *(uint4*)&bx8[0] = *(const uint4*)(XBx + k0);  *(uint4*)&bx8[4] = *(const uint4*)(XBx + k0 + 4);
            *(uint4*)&by8[0] = *(const uint4*)(XBy + k0);  *(uint4*)&by8[4] = *(const uint4*)(XBy + k0 + 4);
        }
#pragma unroll
        for (int kk = 0; kk < 4; ++kk) {
            const uint4 ax = *(const uint4*)&sAx[kk][wr][lane][0];
            const uint4 ay = *(const uint4*)&sAy[kk][wr][lane][0];
#pragma unroll
            for (int tp = 0; tp < 2; ++tp) {
                const uint4 bxv = *(const uint4*)&sBx[kk][wc][tp][lane][0];
                mma_tf32(cx[2 * tp],     ax.x, ax.z, ax.y, ax.w, bxv.x, bxv.y);
                mma_tf32(cx[2 * tp + 1], ax.x, ax.z, ax.y, ax.w, bxv.z, bxv.w);
                const uint4 byv = *(const uint4*)&sBy[kk][wc][tp][lane][0];
                mma_tf32(cy[2 * tp],     ay.x, ay.z, ay.y, ay.w, byv.x, byv.y);
                mma_tf32(cy[2 * tp + 1], ay.x, ay.z, ay.y, ay.w, byv.z, byv.w);
            }
        }
    }

    // -------- Epilogue: distances from gram, fused statistics --------
    const int gr0 = I + 16 * wr + g, gr1 = gr0 + 8;
    const float nIx0 = g_norm[0][gr0], nIx1 = g_norm[0][gr1];
    const float nIy0 = g_norm[1][gr0], nIy1 = g_norm[1][gr1];

    float pxy = 0.f, pxx = 0.f, pyy = 0.f;
    float prx0 = 0.f, prx1 = 0.f, pry0 = 0.f, pry1 = 0.f;

#pragma unroll
    for (int t = 0; t < 4; ++t) {
        const int colL = 32 * wc + 8 * t + 2 * tig;    // local col
        const int gcA = J + colL, gcB = gcA + 1;
        const float nJxA = g_norm[0][gcA], nJxB = g_norm[0][gcB];
        const float nJyA = g_norm[1][gcA], nJyB = g_norm[1][gcB];

        float dx00 = sqrtf(fmaxf(nIx0 + nJxA - 2.f * cx[t][0], 0.f) + 1e-12f);
        float dx01 = sqrtf(fmaxf(nIx0 + nJxB - 2.f * cx[t][1], 0.f) + 1e-12f);
        float dx10 = sqrtf(fmaxf(nIx1 + nJxA - 2.f * cx[t][2], 0.f) + 1e-12f);
        float dx11 = sqrtf(fmaxf(nIx1 + nJxB - 2.f * cx[t][3], 0.f) + 1e-12f);
        float dy00 = sqrtf(fmaxf(nIy0 + nJyA - 2.f * cy[t][0], 0.f) + 1e-12f);
        float dy01 = sqrtf(fmaxf(nIy0 + nJyB - 2.f * cy[t][1], 0.f) + 1e-12f);
        float dy10 = sqrtf(fmaxf(nIy1 + nJyA - 2.f * cy[t][2], 0.f) + 1e-12f);
        float dy11 = sqrtf(fmaxf(nIy1 + nJyB - 2.f * cy[t][3], 0.f) + 1e-12f);

        if (gr0 == gcA) { dx00 = 1e-6f; dy00 = 1e-6f; }   // exact diagonal
        if (gr0 == gcB) { dx01 = 1e-6f; dy01 = 1e-6f; }
        if (gr1 == gcA) { dx10 = 1e-6f; dy10 = 1e-6f; }
        if (gr1 == gcB) { dx11 = 1e-6f; dy11 = 1e-6f; }

        pxy += dx00 * dy00 + dx01 * dy01 + dx10 * dy10 + dx11 * dy11;
        pxx += dx00 * dx00 + dx01 * dx01 + dx10 * dx10 + dx11 * dx11;
        pyy += dy00 * dy00 + dy01 * dy01 + dy10 * dy10 + dy11 * dy11;

        prx0 += dx00 + dx01; prx1 += dx10 + dx11;
        pry0 += dy00 + dy01; pry1 += dy10 + dy11;

        // column sums: combine this thread's two rows, reduce over g (8 lanes)
        float vxA = dx00 + dx10, vxB = dx01 + dx11;
        float vyA = dy00 + dy10, vyB = dy01 + dy11;
#pragma unroll
        for (int s = 16; s >= 4; s >>= 1) {
            vxA += __shfl_down_sync(0xffffffffu, vxA, s);
            vxB += __shfl_down_sync(0xffffffffu, vxB, s);
            vyA += __shfl_down_sync(0xffffffffu, vyA, s);
            vyB += __shfl_down_sync(0xffffffffu, vyB, s);
        }
        if (g == 0) {
            atomicAdd(&sh_cs[0][colL],     vxA);
            atomicAdd(&sh_cs[0][colL + 1], vxB);
            atomicAdd(&sh_cs[1][colL],     vyA);
            atomicAdd(&sh_cs[1][colL + 1], vyB);
        }
    }

    // row sums: reduce over tig (quad)
    prx0 += __shfl_down_sync(0xffffffffu, prx0, 2, 4);
    prx0 += __shfl_down_sync(0xffffffffu, prx0, 1, 4);
    prx1 += __shfl_down_sync(0xffffffffu, prx1, 2, 4);
    prx1 += __shfl_down_sync(0xffffffffu, prx1, 1, 4);
    pry0 += __shfl_down_sync(0xffffffffu, pry0, 2, 4);
    pry0 += __shfl_down_sync(0xffffffffu, pry0, 1, 4);
    pry1 += __shfl_down_sync(0xffffffffu, pry1, 2, 4);
    pry1 += __shfl_down_sync(0xffffffffu, pry1, 1, 4);
    if (tig == 0) {
        atomicAdd(&sh_rs[0][16 * wr + g],     prx0);
        atomicAdd(&sh_rs[0][16 * wr + g + 8], prx1);
        atomicAdd(&sh_rs[1][16 * wr + g],     pry0);
        atomicAdd(&sh_rs[1][16 * wr + g + 8], pry1);
    }

    // scalar products: warp reduce -> shared
#pragma unroll
    for (int off = 16; off > 0; off >>= 1) {
        pxy += __shfl_down_sync(0xffffffffu, pxy, off);
        pxx += __shfl_down_sync(0xffffffffu, pxx, off);
        pyy += __shfl_down_sync(0xffffffffu, pyy, off);
    }
    if (lane == 0) { sh_p[0][warp] = pxy; sh_p[1][warp] = pxx; sh_p[2][warp] = pyy; }
    __syncthreads();

    if (tid < 64) {
        atomicAdd(&g_rs[0][I + tid], sh_rs[0][tid]);
        atomicAdd(&g_rs[1][I + tid], sh_rs[1][tid]);
        if (!diag) {
            atomicAdd(&g_rs[0][J + tid], sh_cs[0][tid]);
            atomicAdd(&g_rs[1][J + tid], sh_cs[1][tid]);
        }
    }
    if (tid == 0) {
        const double scl = diag ? 1.0 : 2.0;
        double s0 = 0, s1 = 0, s2 = 0;
#pragma unroll
        for (int q = 0; q < 8; ++q) { s0 += sh_p[0][q]; s1 += sh_p[1][q]; s2 += sh_p[2][q]; }
        atomicAdd(&g_acc[0], scl * s0);
        atomicAdd(&g_acc[1], scl * s1);
        atomicAdd(&g_acc[2], scl * s2);
    }

    // -------- last-block finalize (threadfence + ticket) --------
    __threadfence();
    __syncthreads();
    if (tid == 0) s_last = (atomicAdd(&g_ticket, 1u) == NBLK - 1) ? 1u : 0u;
    __syncthreads();
    if (s_last == 0u) return;
    __threadfence();

    double sRR = 0.0, sXX = 0.0, sYY = 0.0, sX = 0.0, sY = 0.0;
#pragma unroll
    for (int q = 0; q < 4; ++q) {
        const int i = tid + q * 256;
        const double rx = (double)g_rs[0][i];
        const double ry = (double)g_rs[1][i];
        sRR += rx * ry; sXX += rx * rx; sYY += ry * ry; sX += rx; sY += ry;
    }
#pragma unroll
    for (int off = 16; off > 0; off >>= 1) {
        sRR += __shfl_down_sync(0xffffffffu, sRR, off);
        sXX += __shfl_down_sync(0xffffffffu, sXX, off);
        sYY += __shfl_down_sync(0xffffffffu, sYY, off);
        sX  += __shfl_down_sync(0xffffffffu, sX, off);
        sY  += __shfl_down_sync(0xffffffffu, sY, off);
    }
    __shared__ double sd[5][8];
    if (lane == 0) { sd[0][warp] = sRR; sd[1][warp] = sXX; sd[2][warp] = sYY; sd[3][warp] = sX; sd[4][warp] = sY; }
    __syncthreads();
    if (tid == 0) {
        double a0 = 0, a1 = 0, a2 = 0, a3 = 0, a4 = 0;
#pragma unroll
        for (int q = 0; q < 8; ++q) {
            a0 += sd[0][q]; a1 += sd[1][q]; a2 += sd[2][q]; a3 += sd[3][q]; a4 += sd[4][q];
        }
        const double N = (double)NPTS, N2 = N * N;
        const double sumab = g_acc[0] - (2.0 / N) * a0 + (a3 * a4) / N2;
        const double sumaa = g_acc[1] - (2.0 / N) * a1 + (a3 * a3) / N2;
        const double sumbb = g_acc[2] - (2.0 / N) * a2 + (a4 * a4) / N2;
        const double mxy = sumab / N2, mxx = sumaa / N2, myy = sumbb / N2;
        const double r = mxy / sqrt(mxx * myy + 1e-9);
        out[0] = (float)(1.0 - r);
    }
}

extern "C" void kernel_launch(void* const* d_in, const int* in_sizes, int n_in,
                              void* d_out, int out_size) {
    const float* a = (const float*)d_in[0];  // output_1 (1024,64,256) f32
    const float* b = (const float*)d_in[1];  // feature  (1024,64,256) f32
    // d_in[2] = mask, unused by the reference module.

    mean_norm_kernel<<<dim3(NPTS / 2, 2), 256>>>(a, b);
    gemm_mma_kernel<<<NBLK, 256>>>((float*)d_out);
}